// round 1
// baseline (speedup 1.0000x reference)
#include <cuda_runtime.h>
#include <cstdint>

#define NTHREADS 256
#define ROWLEN   4096
#define KSEL     8
#define POOL_CAP 1024

// Monotone bijection float -> uint32 (order-preserving, larger float = larger uint)
__device__ __forceinline__ unsigned int fflip(float f) {
    unsigned int u = __float_as_uint(f);
    return (u & 0x80000000u) ? ~u : (u | 0x80000000u);
}

__global__ __launch_bounds__(NTHREADS) void kmax_kernel(const float* __restrict__ in,
                                                        float* __restrict__ out) {
    __shared__ float s_gmax[2 * NTHREADS];
    __shared__ unsigned long long s_pool[POOL_CAP];
    __shared__ int s_cnt;
    __shared__ float s_thr;

    const int t = threadIdx.x;
    const size_t row = blockIdx.x;
    const float4* rp = reinterpret_cast<const float4*>(in + row * (size_t)ROWLEN);

    // Front-batched streaming loads: 4x LDG.128 per thread, coalesced across warp.
    float4 v0 = __ldcs(rp + t);
    float4 v1 = __ldcs(rp + 256 + t);
    float4 v2 = __ldcs(rp + 512 + t);
    float4 v3 = __ldcs(rp + 768 + t);

    if (t == 0) s_cnt = 0;

    // Two groups of 8 per thread (partition is arbitrary; only needs to be a partition).
    float g0 = fmaxf(fmaxf(fmaxf(v0.x, v0.y), fmaxf(v0.z, v0.w)),
                     fmaxf(fmaxf(v1.x, v1.y), fmaxf(v1.z, v1.w)));
    float g1 = fmaxf(fmaxf(fmaxf(v2.x, v2.y), fmaxf(v2.z, v2.w)),
                     fmaxf(fmaxf(v3.x, v3.y), fmaxf(v3.z, v3.w)));
    s_gmax[t]            = g0;
    s_gmax[NTHREADS + t] = g1;
    __syncthreads();

    // Warp 0: exact-ish 8th-largest of the 512 group maxes (under-estimates only on
    // duplicate gmax values, which is still a safe superset filter).
    if (t < 32) {
        float r[16];
#pragma unroll
        for (int i = 0; i < 16; i++) r[i] = s_gmax[t * 16 + i];
        float prev = __int_as_float(0x7f800000);  // +inf
#pragma unroll
        for (int k = 0; k < KSEL; k++) {
            float m = __int_as_float(0xff800000);  // -inf
#pragma unroll
            for (int i = 0; i < 16; i++) {
                float c = (r[i] < prev) ? r[i] : __int_as_float(0xff800000);
                m = fmaxf(m, c);
            }
#pragma unroll
            for (int off = 16; off > 0; off >>= 1)
                m = fmaxf(m, __shfl_xor_sync(0xffffffffu, m, off));
            prev = m;
        }
        if (t == 0) s_thr = prev;
    }
    __syncthreads();
    const float thr = s_thr;

    // Push candidate groups (gmax >= thr) into pool as sortable u64 keys:
    // key = flip(val) << 12 | (4095 - idx)  -> max key = (largest val, smallest idx)
    if (g0 >= thr) {
        int base = atomicAdd(&s_cnt, 8);
        if (base + 8 <= POOL_CAP) {
            int iA = 4 * t;            // elements of v0
            int iB = 1024 + 4 * t;     // elements of v1
            s_pool[base + 0] = ((unsigned long long)fflip(v0.x) << 12) | (unsigned)(4095 - (iA + 0));
            s_pool[base + 1] = ((unsigned long long)fflip(v0.y) << 12) | (unsigned)(4095 - (iA + 1));
            s_pool[base + 2] = ((unsigned long long)fflip(v0.z) << 12) | (unsigned)(4095 - (iA + 2));
            s_pool[base + 3] = ((unsigned long long)fflip(v0.w) << 12) | (unsigned)(4095 - (iA + 3));
            s_pool[base + 4] = ((unsigned long long)fflip(v1.x) << 12) | (unsigned)(4095 - (iB + 0));
            s_pool[base + 5] = ((unsigned long long)fflip(v1.y) << 12) | (unsigned)(4095 - (iB + 1));
            s_pool[base + 6] = ((unsigned long long)fflip(v1.z) << 12) | (unsigned)(4095 - (iB + 2));
            s_pool[base + 7] = ((unsigned long long)fflip(v1.w) << 12) | (unsigned)(4095 - (iB + 3));
        }
    }
    if (g1 >= thr) {
        int base = atomicAdd(&s_cnt, 8);
        if (base + 8 <= POOL_CAP) {
            int iA = 2048 + 4 * t;     // elements of v2
            int iB = 3072 + 4 * t;     // elements of v3
            s_pool[base + 0] = ((unsigned long long)fflip(v2.x) << 12) | (unsigned)(4095 - (iA + 0));
            s_pool[base + 1] = ((unsigned long long)fflip(v2.y) << 12) | (unsigned)(4095 - (iA + 1));
            s_pool[base + 2] = ((unsigned long long)fflip(v2.z) << 12) | (unsigned)(4095 - (iA + 2));
            s_pool[base + 3] = ((unsigned long long)fflip(v2.w) << 12) | (unsigned)(4095 - (iA + 3));
            s_pool[base + 4] = ((unsigned long long)fflip(v3.x) << 12) | (unsigned)(4095 - (iB + 0));
            s_pool[base + 5] = ((unsigned long long)fflip(v3.y) << 12) | (unsigned)(4095 - (iB + 1));
            s_pool[base + 6] = ((unsigned long long)fflip(v3.z) << 12) | (unsigned)(4095 - (iB + 2));
            s_pool[base + 7] = ((unsigned long long)fflip(v3.w) << 12) | (unsigned)(4095 - (iB + 3));
        }
    }
    __syncthreads();

    // Warp 0: extract top-8 keys (8 rounds of warp-wide argmax), then write in index order.
    if (t < 32) {
        const int n = min(s_cnt, POOL_CAP);
        unsigned long long mykey = 0ull;
#pragma unroll 1
        for (int k = 0; k < KSEL; k++) {
            unsigned long long best = 0ull;
            int bpos = -1;
            for (int p = t; p < n; p += 32) {
                unsigned long long key = s_pool[p];
                if (key > best) { best = key; bpos = p; }
            }
#pragma unroll
            for (int off = 16; off > 0; off >>= 1) {
                unsigned long long ob = __shfl_xor_sync(0xffffffffu, best, off);
                int op = __shfl_xor_sync(0xffffffffu, bpos, off);
                if (ob > best) { best = ob; bpos = op; }
            }
            if (t == k) mykey = best;          // lane k keeps rank-k winner
            if (t == 0) s_pool[bpos] = 0ull;   // mark used (all keys > 0)
            __syncwarp();
        }
        if (t < KSEL) {
            unsigned int fb = (unsigned int)(mykey >> 12);
            float val = __uint_as_float((fb & 0x80000000u) ? (fb ^ 0x80000000u) : ~fb);
            int idx = 4095 - (int)(mykey & 0xfffu);
            int rank = 0;
#pragma unroll
            for (int j = 0; j < KSEL; j++) {
                int oi = __shfl_sync(0xffu, idx, j);
                rank += (oi < idx);
            }
            out[row * KSEL + rank] = val;
        }
    }
}

extern "C" void kernel_launch(void* const* d_in, const int* in_sizes, int n_in,
                              void* d_out, int out_size) {
    const float* in = (const float*)d_in[0];
    float* out = (float*)d_out;
    int rows = in_sizes[0] / ROWLEN;   // B*C = 16384
    kmax_kernel<<<rows, NTHREADS>>>(in, out);
}